// round 12
// baseline (speedup 1.0000x reference)
#include <cuda_runtime.h>
#include <cstdint>
#include <cfloat>

// Problem constants (fixed by dataset)
#define NN    2048
#define TT    128
#define KSEL  20
#define MAXA  20
#define LRC   0.01f
#define EPSC  1e-8f
#define NW32  (NN/32)
#define MCAP  2560
#define NROWS 4
#define NPAN  (NN/NROWS)   // 512 panel blocks
#define PSTR  2056         // padded panel row stride (floats)

// ---------------- device scratch ---------------------------------------------
__device__ static float    g_B[(TT - 1) * NN];
__device__ static int16_t  g_act_idx[TT * MAXA];
__device__ static int      g_act_cnt[TT];
__device__ static int      g_act_cntfull[TT];
__device__ static unsigned g_act_mask[TT * NW32];
__device__ static unsigned g_match[(TT - 1) * MCAP];   // (js | s1<<8 | c2<<16)
__device__ static int      g_match_cnt[TT - 1];

// ============ K1: top-K, ONE WARP PER TOKEN (no block syncs) =================
#define TKW 4              // warps (tokens) per block
__global__ void __launch_bounds__(TKW * 32)
k_topk(const int* __restrict__ tokens, const float* __restrict__ proj) {
    const int w    = threadIdx.x >> 5;
    const int lane = threadIdx.x & 31;
    const int t    = blockIdx.x * TKW + w;

    __shared__ unsigned hist[TKW][256];
    __shared__ unsigned mask[TKW][NW32];

    // load 64 keys per lane (coalesced float4 per k-group)
    const float4* row4 = reinterpret_cast<const float4*>(
        proj + (size_t)tokens[t] * NN);
    unsigned key[64];
    #pragma unroll
    for (int g = 0; g < 16; g++) {
        const float4 a = row4[g * 32 + lane];
        const float vv[4] = {a.x, a.y, a.z, a.w};
        #pragma unroll
        for (int c = 0; c < 4; c++) {
            unsigned u = __float_as_uint(vv[c]);
            key[g * 4 + c] = (u >> 31) ? ~u : (u | 0x80000000u);
        }
    }

    // zero this warp's histogram
    #pragma unroll
    for (int b = 0; b < 8; b++) hist[w][lane + b * 32] = 0u;
    __syncwarp();

    unsigned prefix = 0u;
    int kk = KSEL;

    #pragma unroll
    for (int bp = 3; bp >= 0; bp--) {
        // count (warp-aggregated atomics into warp-private hist)
        #pragma unroll
        for (int e = 0; e < 64; e++) {
            const bool match =
                (bp == 3) || ((key[e] >> ((bp + 1) * 8)) == prefix);
            const unsigned bin =
                match ? ((key[e] >> (bp * 8)) & 0xFFu) : 0x1FFu;
            const unsigned mk = __match_any_sync(0xFFFFFFFFu, bin);
            if (match && lane == (__ffs(mk) - 1))
                atomicAdd(&hist[w][bin], (unsigned)__popc(mk));
        }
        __syncwarp();

        // warp scan of 256 bins (descending), pick bin containing k-th
        const int top = 255 - lane * 8;
        unsigned local = 0, hv[8];
        #pragma unroll
        for (int q = 0; q < 8; q++) { hv[q] = hist[w][top - q]; local += hv[q]; }
        unsigned incl = local;
        #pragma unroll
        for (int o = 1; o < 32; o <<= 1) {
            unsigned u = __shfl_up_sync(0xFFFFFFFFu, incl, o);
            if (lane >= o) incl += u;
        }
        const unsigned excl = incl - local;
        unsigned my_bin = 0; int my_kk = 0;
        const bool found = (excl < (unsigned)kk) && (incl >= (unsigned)kk);
        if (found) {
            unsigned e = excl;
            #pragma unroll
            for (int q = 0; q < 8; q++) {
                if (e + hv[q] >= (unsigned)kk) {
                    my_bin = (unsigned)(top - q);
                    my_kk  = kk - (int)e;
                    break;
                }
                e += hv[q];
            }
        }
        const unsigned fb = __ballot_sync(0xFFFFFFFFu, found);
        const int src = __ffs(fb) - 1;
        prefix = (prefix << 8) | __shfl_sync(0xFFFFFFFFu, my_bin, src);
        kk     = __shfl_sync(0xFFFFFFFFu, my_kk, src);

        // re-zero for next pass
        #pragma unroll
        for (int q = 0; q < 8; q++) hist[w][top - q] = 0u;
        __syncwarp();
    }
    const unsigned thr = prefix;

    // zero warp-private mask
    mask[w][lane] = 0u; mask[w][lane + 32] = 0u;
    __syncwarp();

    // compaction: ballot per element group, deterministic positions
    int total = 0;
    #pragma unroll
    for (int g = 0; g < 16; g++) {
        #pragma unroll
        for (int c = 0; c < 4; c++) {
            const bool pred = key[g * 4 + c] >= thr;
            const unsigned bal = __ballot_sync(0xFFFFFFFFu, pred);
            if (pred) {
                const int i = g * 128 + lane * 4 + c;
                atomicOr(&mask[w][i >> 5], 1u << (i & 31));
                const int pos = total + __popc(bal & ((1u << lane) - 1u));
                if (pos < MAXA) g_act_idx[t * MAXA + pos] = (int16_t)i;
            }
            total += __popc(bal);
        }
    }
    __syncwarp();

    const int cc = (total < MAXA) ? total : MAXA;
    if (lane >= cc && lane < MAXA) g_act_idx[t * MAXA + lane] = 0;  // pad
    g_act_mask[t * NW32 + lane]      = mask[w][lane];
    g_act_mask[t * NW32 + lane + 32] = mask[w][lane + 32];
    if (lane == 0) { g_act_cntfull[t] = total; g_act_cnt[t] = cc; }
}

// ====== K2: blocks 0..511 = panel sums -> g_B ; blocks 512..638 = match lists =
__global__ void __launch_bounds__(512)
k_mid(const float* __restrict__ S, const int* __restrict__ plast) {
    const int bx  = blockIdx.x;
    const int tid = threadIdx.x;
    __shared__ __align__(16) char s_raw[40832];
    // panel 32896 @0 | idx 5120 @32896 | acnt 128 @38016 | pos 2048 @38144 | cntp @40192
    float*   panel = reinterpret_cast<float*>(s_raw);
    int16_t* idx   = reinterpret_cast<int16_t*>(s_raw + 32896);
    uint8_t* acnt  = reinterpret_cast<uint8_t*>(s_raw + 38016);
    uint8_t* pos   = reinterpret_cast<uint8_t*>(s_raw + 38144);
    int*     cntp  = reinterpret_cast<int*>(s_raw + 40192);

    for (int x = tid; x < TT * MAXA / 2; x += 512)
        reinterpret_cast<int*>(idx)[x] = reinterpret_cast<const int*>(g_act_idx)[x];
    if (tid < TT) acnt[tid] = (uint8_t)g_act_cnt[tid];

    if (bx < NPAN) {
        // ---- one block per 4-row sigma panel ----
        const int i0   = bx * NROWS;
        const int srow = tid >> 7;
        const int scol = (tid & 127) * 4;
        #pragma unroll
        for (int k = 0; k < 4; k++) {
            const float4 sv = *reinterpret_cast<const float4*>(
                S + (size_t)(i0 + srow) * NN + scol + k * 512);
            *reinterpret_cast<float4*>(panel + srow * PSTR + scol + k * 512) = sv;
        }
        __syncthreads();

        if (tid < (TT - 1) * NROWS) {
            const int my_t  = tid >> 2;
            const int my_il = tid & 3;
            const int cnt   = (int)acnt[my_t];
            const float* prow = panel + my_il * PSTR;
            int jreg[MAXA];
            #pragma unroll
            for (int m = 0; m < MAXA; m++) jreg[m] = (int)idx[my_t * MAXA + m];
            float sum = 0.f;
            #pragma unroll
            for (int m = 0; m < MAXA; m++) {
                const float val = prow[jreg[m]];
                if (m < cnt) sum += val;
            }
            g_B[my_t * NN + i0 + my_il] = sum;
        }
        return;
    }

    // ---- match list for t = bx - NPAN ----
    const int t = bx - NPAN;
    if (!*plast) { if (tid == 0) g_match_cnt[t] = 0; return; }
    for (int x = tid; x < NN / 4; x += 512)
        reinterpret_cast<unsigned*>(pos)[x] = 0xFFFFFFFFu;
    if (tid == 0) *cntp = 0;
    __syncthreads();
    if (tid < (int)acnt[t]) pos[(int)idx[t * MAXA + tid]] = (uint8_t)tid;
    __syncthreads();
    for (int wk = tid; wk < t * 32; wk += 512) {
        const int s = wk >> 5;
        const int m = wk & 31;
        if (m < (int)acnt[s]) {
            const int j  = (int)idx[s * MAXA + m];
            const int js = pos[j];
            if (js != 0xFF) {
                const int p = atomicAdd(cntp, 1);
                g_match[t * MCAP + p] =
                    (unsigned)js | ((unsigned)(s + 1) << 8) |
                    ((unsigned)acnt[s + 1] << 16);
            }
        }
    }
    __syncthreads();
    if (tid == 0) g_match_cnt[t] = *cntp;
}

// ================= K3: tension, one block per t (full row, no combine) =======
__global__ void __launch_bounds__(512)
k_tension(const float* __restrict__ S, const int* __restrict__ plast,
          float* __restrict__ out) {
    const int t    = blockIdx.x;
    const int tid  = threadIdx.x;
    const int lane = tid & 31;
    const int w    = tid >> 5;
    const int i0   = tid * 4;

    __shared__ __align__(16) char s_raw[46336];
    // cw 40960 @0 | idx 5120 @40960 | red 128 @46080
    unsigned* cw  = reinterpret_cast<unsigned*>(s_raw);
    int16_t*  idx = reinterpret_cast<int16_t*>(s_raw + 40960);
    float*    red = reinterpret_cast<float*>(s_raw + 46080);

    const int pl = *plast;

    for (int x = tid; x < TT * MAXA / 2; x += 512)
        reinterpret_cast<int*>(idx)[x] = reinterpret_cast<const int*>(g_act_idx)[x];
    if (pl)
        for (int x = tid; x < MAXA * NN / 4; x += 512) cw[x] = 0u;

    const float4 a4 = *reinterpret_cast<const float4*>(g_B + t * NN + i0);
    float p[4] = {a4.x, a4.y, a4.z, a4.w};

    if (pl) {
        __syncthreads();
        const int nm = g_match_cnt[t];
        for (int e = tid; e < nm; e += 512) {
            const unsigned ent = g_match[t * MCAP + e];
            const int js = (int)(ent & 0xFFu);
            const int b2 = (int)((ent >> 8) & 0xFFu) * MAXA;
            const int c2 = (int)(ent >> 16);
            for (int mm = 0; mm < c2; mm++) {
                const unsigned i = (unsigned)(int)idx[b2 + mm];
                const unsigned off = (unsigned)js * NN + i;
                atomicAdd(&cw[off >> 2], 1u << ((off & 3u) * 8u));
            }
        }
        __syncthreads();

        #pragma unroll
        for (int js = 0; js < MAXA; js++) {
            const unsigned w0 = cw[js * (NN / 4) + tid];
            if (w0) {
                const int j = (int)idx[t * MAXA + js];
                #pragma unroll
                for (int c = 0; c < 4; c++) {
                    const unsigned cc = (w0 >> (c * 8)) & 0xFFu;
                    if (cc) {
                        const float v = S[(size_t)(i0 + c) * NN + j];
                        p[c] += fminf(v + LRC * (float)cc, 1.0f) - v;
                    }
                }
            }
        }
    }

    const unsigned mword = g_act_mask[(t + 1) * NW32 + (i0 >> 5)];
    const unsigned nib = (mword >> (i0 & 31)) & 0xFu;
    float pn2 = 0.f, dt = 0.f;
    #pragma unroll
    for (int c = 0; c < 4; c++) {
        pn2 += p[c] * p[c];
        if ((nib >> c) & 1u) dt += p[c];
    }
    #pragma unroll
    for (int o = 16; o; o >>= 1) {
        pn2 += __shfl_xor_sync(0xFFFFFFFFu, pn2, o);
        dt  += __shfl_xor_sync(0xFFFFFFFFu, dt, o);
    }
    __syncthreads();
    if (lane == 0) { red[2 * w] = pn2; red[2 * w + 1] = dt; }
    __syncthreads();
    if (tid == 0) {
        float P2 = 0.f, D = 0.f;
        #pragma unroll
        for (int r = 0; r < 16; r++) { P2 += red[2 * r]; D += red[2 * r + 1]; }
        const float pn = sqrtf(P2);
        float tension;
        if (pl) {
            const float overlap = D / (pn * sqrtf((float)KSEL) + EPSC);
            tension = (pn > 0.0f) ? (1.0f - overlap) : 1.0f;
        } else {
            const float xn = sqrtf((float)g_act_cntfull[t + 1]);
            tension = 1.0f - D / (pn * xn + EPSC);
        }
        out[t] = tension;
    }
}

// ---------------- launch ------------------------------------------------------
extern "C" void kernel_launch(void* const* d_in, const int* in_sizes, int n_in,
                              void* d_out, int out_size) {
    const int*   tokens = (const int*)d_in[0];
    const float* proj   = (const float*)d_in[1];
    const float* sigma  = (const float*)d_in[2];
    const int*   plast  = (const int*)d_in[3];
    float*       out    = (float*)d_out;

    k_topk<<<TT / TKW, TKW * 32>>>(tokens, proj);
    k_mid<<<NPAN + (TT - 1), 512>>>(sigma, plast);
    k_tension<<<TT - 1, 512>>>(sigma, plast, out);
}

// round 13
// speedup vs baseline: 1.6043x; 1.6043x over previous
#include <cuda_runtime.h>
#include <cstdint>
#include <cfloat>

// Problem constants (fixed by dataset)
#define NN    2048
#define TT    128
#define KSEL  20
#define MAXA  20
#define LRC   0.01f
#define EPSC  1e-8f
#define NW32  (NN/32)
#define MCAP  2560
#define NROWS 4
#define NPAN  (NN/NROWS)   // 512 panel blocks
#define PSTR  2056         // padded panel row stride (floats)

// ---------------- device scratch ---------------------------------------------
__device__ static float    g_B[(TT - 1) * NN];
__device__ static int16_t  g_act_idx[TT * MAXA];
__device__ static int      g_act_cnt[TT];
__device__ static int      g_act_cntfull[TT];
__device__ static unsigned g_act_mask[TT * NW32];
__device__ static unsigned g_match[(TT - 1) * MCAP];   // (js | s1<<8 | c2<<16)
__device__ static int      g_match_cnt[TT - 1];

// ========= K1: top-K, one block/token, 1-pass 2048-bin radix + resolve =======
__global__ void __launch_bounds__(512)
k_topk(const int* __restrict__ tokens, const float* __restrict__ proj) {
    const int t    = blockIdx.x;
    const int tid  = threadIdx.x;
    const int lane = tid & 31;
    const int wid  = tid >> 5;

    __shared__ unsigned hist[2048];     // 8 KB
    __shared__ unsigned wsum[16];
    __shared__ unsigned cand[32];
    __shared__ unsigned smask[NW32];
    __shared__ unsigned s_bin, s_thr;
    __shared__ int      s_kk2, s_bc, s_nc, s_cnt;

    const float4 a = *reinterpret_cast<const float4*>(
        proj + (size_t)tokens[t] * NN + tid * 4);
    const float vv[4] = {a.x, a.y, a.z, a.w};
    unsigned key[4];
    #pragma unroll
    for (int m = 0; m < 4; m++) {
        const unsigned u = __float_as_uint(vv[m]);
        key[m] = (u >> 31) ? ~u : (u | 0x80000000u);   // monotone map
    }

    unsigned prefix = 0u, thr = 0u, Tlev = NN;
    int kkcur = KSEL;

    #pragma unroll
    for (int level = 0; level < 3; level++) {
        const int      SH = (level == 0) ? 21 : ((level == 1) ? 10 : 0);
        const int      WB = (level == 2) ? 10 : 11;
        const unsigned WM = (level == 2) ? 0x3FFu : 0x7FFu;

        reinterpret_cast<uint4*>(hist)[tid] = make_uint4(0u, 0u, 0u, 0u);
        __syncthreads();

        #pragma unroll
        for (int m = 0; m < 4; m++) {
            const bool part =
                (level == 0) || ((key[m] >> (SH + WB)) == prefix);
            const unsigned bin = part ? ((key[m] >> SH) & WM) : 0xFFFFu;
            const unsigned mk  = __match_any_sync(0xFFFFFFFFu, bin);
            if (part && lane == (__ffs(mk) - 1))
                atomicAdd(&hist[bin], (unsigned)__popc(mk));
        }
        __syncthreads();

        // block scan of 2048 bins (ascending), locate boundary bin
        const uint4 h4 = reinterpret_cast<const uint4*>(hist)[tid];
        const unsigned hv[4] = {h4.x, h4.y, h4.z, h4.w};
        const unsigned lsum = hv[0] + hv[1] + hv[2] + hv[3];
        unsigned incl = lsum;
        #pragma unroll
        for (int o = 1; o < 32; o <<= 1) {
            const unsigned u = __shfl_up_sync(0xFFFFFFFFu, incl, o);
            if (lane >= o) incl += u;
        }
        if (lane == 31) wsum[wid] = incl;
        if (tid == 0) s_nc = 0;
        __syncthreads();
        unsigned woff = 0u;
        for (int q = 0; q < wid; q++) woff += wsum[q];
        unsigned e = woff + incl - lsum;           // exclusive prefix of bin 4tid
        const unsigned target = Tlev - (unsigned)kkcur;
        #pragma unroll
        for (int c = 0; c < 4; c++) {
            const unsigned hb = hv[c];
            if (hb && e <= target && target < e + hb) {
                s_bin = (unsigned)(tid * 4 + c);
                s_kk2 = kkcur - (int)(Tlev - e - hb);
                s_bc  = (int)hb;
            }
            e += hb;
        }
        __syncthreads();

        prefix = (prefix << WB) | s_bin;
        kkcur  = s_kk2;
        const int bc = s_bc;
        Tlev = (unsigned)bc;

        if (level == 2) { thr = prefix; break; }   // 32 bits exhausted: exact
        if (bc <= 32) {
            // collect boundary-bin candidates, resolve kk-th largest exactly
            #pragma unroll
            for (int m = 0; m < 4; m++) {
                if ((key[m] >> SH) == prefix) {
                    const int p = atomicAdd(&s_nc, 1);
                    cand[p] = key[m];              // p < bc <= 32
                }
            }
            __syncthreads();
            if (tid < 32) {
                const int nc = s_nc;
                const unsigned c = (lane < nc) ? cand[lane] : 0u;
                int g = 0, eq = 0;
                for (int j = 0; j < nc; j++) {
                    const unsigned v = cand[j];
                    g  += (v > c);
                    eq += (v == c);
                }
                if (lane < nc && g < kkcur && kkcur <= g + eq) s_thr = c;
            }
            __syncthreads();
            thr = s_thr;
            break;
        }
    }

    // build mask + index list: key >= thr  (== raw >= value-threshold)
    if (tid < NW32) smask[tid] = 0u;
    if (tid == 0)   s_cnt = 0;
    __syncthreads();
    #pragma unroll
    for (int m = 0; m < 4; m++) {
        if (key[m] >= thr) {
            const int i = tid * 4 + m;
            atomicOr(&smask[i >> 5], 1u << (i & 31));
            const int p = atomicAdd(&s_cnt, 1);
            if (p < MAXA) g_act_idx[t * MAXA + p] = (int16_t)i;
        }
    }
    __syncthreads();
    const int cnt = s_cnt;
    const int cc  = (cnt < MAXA) ? cnt : MAXA;
    if (tid >= cc && tid < MAXA) g_act_idx[t * MAXA + tid] = 0;   // pad for unroll
    if (tid < NW32) g_act_mask[t * NW32 + tid] = smask[tid];
    if (tid == 0) { g_act_cntfull[t] = cnt; g_act_cnt[t] = cc; }
}

// ====== K2: blocks 0..511 = panel sums -> g_B ; blocks 512..638 = match lists =
__global__ void __launch_bounds__(512)
k_mid(const float* __restrict__ S, const int* __restrict__ plast) {
    const int bx  = blockIdx.x;
    const int tid = threadIdx.x;
    __shared__ __align__(16) char s_raw[40832];
    // panel 32896 @0 | idx 5120 @32896 | acnt 128 @38016 | pos 2048 @38144 | cntp @40192
    float*   panel = reinterpret_cast<float*>(s_raw);
    int16_t* idx   = reinterpret_cast<int16_t*>(s_raw + 32896);
    uint8_t* acnt  = reinterpret_cast<uint8_t*>(s_raw + 38016);
    uint8_t* pos   = reinterpret_cast<uint8_t*>(s_raw + 38144);
    int*     cntp  = reinterpret_cast<int*>(s_raw + 40192);

    for (int x = tid; x < TT * MAXA / 2; x += 512)
        reinterpret_cast<int*>(idx)[x] = reinterpret_cast<const int*>(g_act_idx)[x];
    if (tid < TT) acnt[tid] = (uint8_t)g_act_cnt[tid];

    if (bx < NPAN) {
        // ---- one block per 4-row sigma panel ----
        const int i0   = bx * NROWS;
        const int srow = tid >> 7;
        const int scol = (tid & 127) * 4;
        #pragma unroll
        for (int k = 0; k < 4; k++) {
            const float4 sv = *reinterpret_cast<const float4*>(
                S + (size_t)(i0 + srow) * NN + scol + k * 512);
            *reinterpret_cast<float4*>(panel + srow * PSTR + scol + k * 512) = sv;
        }
        __syncthreads();

        if (tid < (TT - 1) * NROWS) {
            const int my_t  = tid >> 2;
            const int my_il = tid & 3;
            const int cnt   = (int)acnt[my_t];
            const float* prow = panel + my_il * PSTR;
            int jreg[MAXA];
            #pragma unroll
            for (int m = 0; m < MAXA; m++) jreg[m] = (int)idx[my_t * MAXA + m];
            float sum = 0.f;
            #pragma unroll
            for (int m = 0; m < MAXA; m++) {
                const float val = prow[jreg[m]];
                if (m < cnt) sum += val;
            }
            g_B[my_t * NN + i0 + my_il] = sum;
        }
        return;
    }

    // ---- match list for t = bx - NPAN ----
    const int t = bx - NPAN;
    if (!*plast) { if (tid == 0) g_match_cnt[t] = 0; return; }
    for (int x = tid; x < NN / 4; x += 512)
        reinterpret_cast<unsigned*>(pos)[x] = 0xFFFFFFFFu;
    if (tid == 0) *cntp = 0;
    __syncthreads();
    if (tid < (int)acnt[t]) pos[(int)idx[t * MAXA + tid]] = (uint8_t)tid;
    __syncthreads();
    for (int wk = tid; wk < t * 32; wk += 512) {
        const int s = wk >> 5;
        const int m = wk & 31;
        if (m < (int)acnt[s]) {
            const int j  = (int)idx[s * MAXA + m];
            const int js = pos[j];
            if (js != 0xFF) {
                const int p = atomicAdd(cntp, 1);
                g_match[t * MCAP + p] =
                    (unsigned)js | ((unsigned)(s + 1) << 8) |
                    ((unsigned)acnt[s + 1] << 16);
            }
        }
    }
    __syncthreads();
    if (tid == 0) g_match_cnt[t] = *cntp;
}

// ================= K3: tension, one block per t (full row, no combine) =======
__global__ void __launch_bounds__(512)
k_tension(const float* __restrict__ S, const int* __restrict__ plast,
          float* __restrict__ out) {
    const int t    = blockIdx.x;
    const int tid  = threadIdx.x;
    const int lane = tid & 31;
    const int w    = tid >> 5;
    const int i0   = tid * 4;

    __shared__ __align__(16) char s_raw[46336];
    // cw 40960 @0 | idx 5120 @40960 | red 128 @46080
    unsigned* cw  = reinterpret_cast<unsigned*>(s_raw);
    int16_t*  idx = reinterpret_cast<int16_t*>(s_raw + 40960);
    float*    red = reinterpret_cast<float*>(s_raw + 46080);

    const int pl = *plast;

    for (int x = tid; x < TT * MAXA / 2; x += 512)
        reinterpret_cast<int*>(idx)[x] = reinterpret_cast<const int*>(g_act_idx)[x];
    if (pl)
        for (int x = tid; x < MAXA * NN / 4; x += 512) cw[x] = 0u;

    const float4 a4 = *reinterpret_cast<const float4*>(g_B + t * NN + i0);
    float p[4] = {a4.x, a4.y, a4.z, a4.w};

    if (pl) {
        __syncthreads();
        const int nm = g_match_cnt[t];
        for (int e = tid; e < nm; e += 512) {
            const unsigned ent = g_match[t * MCAP + e];
            const int js = (int)(ent & 0xFFu);
            const int b2 = (int)((ent >> 8) & 0xFFu) * MAXA;
            const int c2 = (int)(ent >> 16);
            for (int mm = 0; mm < c2; mm++) {
                const unsigned i = (unsigned)(int)idx[b2 + mm];
                const unsigned off = (unsigned)js * NN + i;
                atomicAdd(&cw[off >> 2], 1u << ((off & 3u) * 8u));
            }
        }
        __syncthreads();

        #pragma unroll
        for (int js = 0; js < MAXA; js++) {
            const unsigned w0 = cw[js * (NN / 4) + tid];
            if (w0) {
                const int j = (int)idx[t * MAXA + js];
                #pragma unroll
                for (int c = 0; c < 4; c++) {
                    const unsigned cc = (w0 >> (c * 8)) & 0xFFu;
                    if (cc) {
                        const float v = S[(size_t)(i0 + c) * NN + j];
                        p[c] += fminf(v + LRC * (float)cc, 1.0f) - v;
                    }
                }
            }
        }
    }

    const unsigned mword = g_act_mask[(t + 1) * NW32 + (i0 >> 5)];
    const unsigned nib = (mword >> (i0 & 31)) & 0xFu;
    float pn2 = 0.f, dt = 0.f;
    #pragma unroll
    for (int c = 0; c < 4; c++) {
        pn2 += p[c] * p[c];
        if ((nib >> c) & 1u) dt += p[c];
    }
    #pragma unroll
    for (int o = 16; o; o >>= 1) {
        pn2 += __shfl_xor_sync(0xFFFFFFFFu, pn2, o);
        dt  += __shfl_xor_sync(0xFFFFFFFFu, dt, o);
    }
    __syncthreads();
    if (lane == 0) { red[2 * w] = pn2; red[2 * w + 1] = dt; }
    __syncthreads();
    if (tid == 0) {
        float P2 = 0.f, D = 0.f;
        #pragma unroll
        for (int r = 0; r < 16; r++) { P2 += red[2 * r]; D += red[2 * r + 1]; }
        const float pn = sqrtf(P2);
        float tension;
        if (pl) {
            const float overlap = D / (pn * sqrtf((float)KSEL) + EPSC);
            tension = (pn > 0.0f) ? (1.0f - overlap) : 1.0f;
        } else {
            const float xn = sqrtf((float)g_act_cntfull[t + 1]);
            tension = 1.0f - D / (pn * xn + EPSC);
        }
        out[t] = tension;
    }
}

// ---------------- launch ------------------------------------------------------
extern "C" void kernel_launch(void* const* d_in, const int* in_sizes, int n_in,
                              void* d_out, int out_size) {
    const int*   tokens = (const int*)d_in[0];
    const float* proj   = (const float*)d_in[1];
    const float* sigma  = (const float*)d_in[2];
    const int*   plast  = (const int*)d_in[3];
    float*       out    = (float*)d_out;

    k_topk<<<TT, 512>>>(tokens, proj);
    k_mid<<<NPAN + (TT - 1), 512>>>(sigma, plast);
    k_tension<<<TT - 1, 512>>>(sigma, plast, out);
}

// round 14
// speedup vs baseline: 1.6459x; 1.0259x over previous
#include <cuda_runtime.h>
#include <cstdint>
#include <cfloat>

// Problem constants (fixed by dataset)
#define NN    2048
#define TT    128
#define KSEL  20
#define MAXA  20
#define LRC   0.01f
#define EPSC  1e-8f
#define NW32  (NN/32)
#define NROWS 4
#define NPAN  (NN/NROWS)   // 512 panel blocks
#define PSTR  2056         // padded panel row stride (floats)

// ---------------- device scratch ---------------------------------------------
__device__ static float    g_B[(TT - 1) * NN];
__device__ static int16_t  g_act_idx[TT * MAXA];
__device__ static int      g_act_cnt[TT];
__device__ static int      g_act_cntfull[TT];
__device__ static unsigned g_act_mask[TT * NW32];

// ========= K1: top-K, one block/token, 1-pass 2048-bin radix + resolve =======
__global__ void __launch_bounds__(512)
k_topk(const int* __restrict__ tokens, const float* __restrict__ proj) {
    const int t    = blockIdx.x;
    const int tid  = threadIdx.x;
    const int lane = tid & 31;
    const int wid  = tid >> 5;

    __shared__ unsigned hist[2048];     // 8 KB
    __shared__ unsigned wsum[16];
    __shared__ unsigned cand[32];
    __shared__ unsigned smask[NW32];
    __shared__ unsigned s_bin, s_thr;
    __shared__ int      s_kk2, s_bc, s_nc, s_cnt;

    const float4 a = *reinterpret_cast<const float4*>(
        proj + (size_t)tokens[t] * NN + tid * 4);
    const float vv[4] = {a.x, a.y, a.z, a.w};
    unsigned key[4];
    #pragma unroll
    for (int m = 0; m < 4; m++) {
        const unsigned u = __float_as_uint(vv[m]);
        key[m] = (u >> 31) ? ~u : (u | 0x80000000u);   // monotone map
    }

    unsigned prefix = 0u, thr = 0u, Tlev = NN;
    int kkcur = KSEL;

    #pragma unroll
    for (int level = 0; level < 3; level++) {
        const int      SH = (level == 0) ? 21 : ((level == 1) ? 10 : 0);
        const int      WB = (level == 2) ? 10 : 11;
        const unsigned WM = (level == 2) ? 0x3FFu : 0x7FFu;

        reinterpret_cast<uint4*>(hist)[tid] = make_uint4(0u, 0u, 0u, 0u);
        __syncthreads();

        #pragma unroll
        for (int m = 0; m < 4; m++) {
            const bool part =
                (level == 0) || ((key[m] >> (SH + WB)) == prefix);
            const unsigned bin = part ? ((key[m] >> SH) & WM) : 0xFFFFu;
            const unsigned mk  = __match_any_sync(0xFFFFFFFFu, bin);
            if (part && lane == (__ffs(mk) - 1))
                atomicAdd(&hist[bin], (unsigned)__popc(mk));
        }
        __syncthreads();

        // block scan of 2048 bins (ascending), locate boundary bin
        const uint4 h4 = reinterpret_cast<const uint4*>(hist)[tid];
        const unsigned hv[4] = {h4.x, h4.y, h4.z, h4.w};
        const unsigned lsum = hv[0] + hv[1] + hv[2] + hv[3];
        unsigned incl = lsum;
        #pragma unroll
        for (int o = 1; o < 32; o <<= 1) {
            const unsigned u = __shfl_up_sync(0xFFFFFFFFu, incl, o);
            if (lane >= o) incl += u;
        }
        if (lane == 31) wsum[wid] = incl;
        if (tid == 0) s_nc = 0;
        __syncthreads();
        unsigned woff = 0u;
        for (int q = 0; q < wid; q++) woff += wsum[q];
        unsigned e = woff + incl - lsum;           // exclusive prefix of bin 4tid
        const unsigned target = Tlev - (unsigned)kkcur;
        #pragma unroll
        for (int c = 0; c < 4; c++) {
            const unsigned hb = hv[c];
            if (hb && e <= target && target < e + hb) {
                s_bin = (unsigned)(tid * 4 + c);
                s_kk2 = kkcur - (int)(Tlev - e - hb);
                s_bc  = (int)hb;
            }
            e += hb;
        }
        __syncthreads();

        prefix = (prefix << WB) | s_bin;
        kkcur  = s_kk2;
        const int bc = s_bc;
        Tlev = (unsigned)bc;

        if (level == 2) { thr = prefix; break; }   // 32 bits exhausted: exact
        if (bc <= 32) {
            #pragma unroll
            for (int m = 0; m < 4; m++) {
                if ((key[m] >> SH) == prefix) {
                    const int p = atomicAdd(&s_nc, 1);
                    cand[p] = key[m];              // p < bc <= 32
                }
            }
            __syncthreads();
            if (tid < 32) {
                const int nc = s_nc;
                const unsigned c = (lane < nc) ? cand[lane] : 0u;
                int g = 0, eq = 0;
                for (int j = 0; j < nc; j++) {
                    const unsigned v = cand[j];
                    g  += (v > c);
                    eq += (v == c);
                }
                if (lane < nc && g < kkcur && kkcur <= g + eq) s_thr = c;
            }
            __syncthreads();
            thr = s_thr;
            break;
        }
    }

    // build mask + index list: key >= thr
    if (tid < NW32) smask[tid] = 0u;
    if (tid == 0)   s_cnt = 0;
    __syncthreads();
    #pragma unroll
    for (int m = 0; m < 4; m++) {
        if (key[m] >= thr) {
            const int i = tid * 4 + m;
            atomicOr(&smask[i >> 5], 1u << (i & 31));
            const int p = atomicAdd(&s_cnt, 1);
            if (p < MAXA) g_act_idx[t * MAXA + p] = (int16_t)i;
        }
    }
    __syncthreads();
    const int cnt = s_cnt;
    const int cc  = (cnt < MAXA) ? cnt : MAXA;
    if (tid >= cc && tid < MAXA) g_act_idx[t * MAXA + tid] = 0;   // pad for unroll
    if (tid < NW32) g_act_mask[t * NW32 + tid] = smask[tid];
    if (tid == 0) { g_act_cntfull[t] = cnt; g_act_cnt[t] = cc; }
}

// ====== K2: 512 panel blocks -> g_B (PDL: sigma staged BEFORE dependency) ====
__global__ void __launch_bounds__(512)
k_mid(const float* __restrict__ S) {
    const int bx  = blockIdx.x;
    const int tid = threadIdx.x;
    __shared__ __align__(16) char s_raw[38144];
    // panel 32896 @0 | idx 5120 @32896 | acnt 128 @38016
    float*   panel = reinterpret_cast<float*>(s_raw);
    int16_t* idx   = reinterpret_cast<int16_t*>(s_raw + 32896);
    uint8_t* acnt  = reinterpret_cast<uint8_t*>(s_raw + 38016);

    // ---- prologue: stage sigma panel (independent of k_topk) ----
    const int i0   = bx * NROWS;
    const int srow = tid >> 7;
    const int scol = (tid & 127) * 4;
    #pragma unroll
    for (int k = 0; k < 4; k++) {
        const float4 sv = *reinterpret_cast<const float4*>(
            S + (size_t)(i0 + srow) * NN + scol + k * 512);
        *reinterpret_cast<float4*>(panel + srow * PSTR + scol + k * 512) = sv;
    }

    // ---- wait for k_topk results ----
    cudaGridDependencySynchronize();

    for (int x = tid; x < TT * MAXA / 2; x += 512)
        reinterpret_cast<int*>(idx)[x] = reinterpret_cast<const int*>(g_act_idx)[x];
    if (tid < TT) acnt[tid] = (uint8_t)g_act_cnt[tid];
    __syncthreads();

    if (tid < (TT - 1) * NROWS) {
        const int my_t  = tid >> 2;
        const int my_il = tid & 3;
        const int cnt   = (int)acnt[my_t];
        const float* prow = panel + my_il * PSTR;
        int jreg[MAXA];
        #pragma unroll
        for (int m = 0; m < MAXA; m++) jreg[m] = (int)idx[my_t * MAXA + m];
        float sum = 0.f;
        #pragma unroll
        for (int m = 0; m < MAXA; m++) {
            const float val = prow[jreg[m]];
            if (m < cnt) sum += val;
        }
        g_B[my_t * NN + i0 + my_il] = sum;
    }
}

// ==== K3: tension per t; inline match scan; PDL (cw zeroing before sync) =====
__global__ void __launch_bounds__(512)
k_tension(const float* __restrict__ S, const int* __restrict__ plast,
          float* __restrict__ out) {
    const int t    = blockIdx.x;
    const int tid  = threadIdx.x;
    const int lane = tid & 31;
    const int w    = tid >> 5;
    const int i0   = tid * 4;

    __shared__ __align__(16) char s_raw[48384];
    // cw 40960 @0 | idx 5120 @40960 | acnt 128 @46080 | pos 2048 @46208 | red @48256
    unsigned* cw   = reinterpret_cast<unsigned*>(s_raw);
    int16_t*  idx  = reinterpret_cast<int16_t*>(s_raw + 40960);
    uint8_t*  acnt = reinterpret_cast<uint8_t*>(s_raw + 46080);
    uint8_t*  pos  = reinterpret_cast<uint8_t*>(s_raw + 46208);
    float*    red  = reinterpret_cast<float*>(s_raw + 48256);

    // ---- prologue (independent of upstream kernels) ----
    const int pl = *plast;
    if (pl)
        for (int x = tid; x < MAXA * NN / 4; x += 512) cw[x] = 0u;
    if (tid < NN / 4) reinterpret_cast<unsigned*>(pos)[tid] = 0xFFFFFFFFu;

    // ---- wait for k_mid (and transitively k_topk) ----
    cudaGridDependencySynchronize();

    for (int x = tid; x < TT * MAXA / 2; x += 512)
        reinterpret_cast<int*>(idx)[x] = reinterpret_cast<const int*>(g_act_idx)[x];
    if (tid < TT) acnt[tid] = (uint8_t)g_act_cnt[tid];
    __syncthreads();
    if (tid < (int)acnt[t]) pos[(int)idx[t * MAXA + tid]] = (uint8_t)tid;
    __syncthreads();

    const float4 a4 = *reinterpret_cast<const float4*>(g_B + t * NN + i0);
    float p[4] = {a4.x, a4.y, a4.z, a4.w};

    if (pl) {
        // inline match scan + count expansion (~4 scan items/thread)
        for (int wk = tid; wk < t * 32; wk += 512) {
            const int s = wk >> 5;
            const int m = wk & 31;
            if (m < (int)acnt[s]) {
                const int j  = (int)idx[s * MAXA + m];
                const int js = pos[j];
                if (js != 0xFF) {
                    const int c2 = (int)acnt[s + 1];
                    const int b2 = (s + 1) * MAXA;
                    for (int mm = 0; mm < c2; mm++) {
                        const unsigned i = (unsigned)(int)idx[b2 + mm];
                        const unsigned off = (unsigned)js * NN + i;
                        atomicAdd(&cw[off >> 2], 1u << ((off & 3u) * 8u));
                    }
                }
            }
        }
        __syncthreads();

        #pragma unroll
        for (int js = 0; js < MAXA; js++) {
            const unsigned w0 = cw[js * (NN / 4) + tid];
            if (w0) {
                const int j = (int)idx[t * MAXA + js];
                #pragma unroll
                for (int c = 0; c < 4; c++) {
                    const unsigned cc = (w0 >> (c * 8)) & 0xFFu;
                    if (cc) {
                        const float v = S[(size_t)(i0 + c) * NN + j];
                        p[c] += fminf(v + LRC * (float)cc, 1.0f) - v;
                    }
                }
            }
        }
    }

    const unsigned mword = g_act_mask[(t + 1) * NW32 + (i0 >> 5)];
    const unsigned nib = (mword >> (i0 & 31)) & 0xFu;
    float pn2 = 0.f, dt = 0.f;
    #pragma unroll
    for (int c = 0; c < 4; c++) {
        pn2 += p[c] * p[c];
        if ((nib >> c) & 1u) dt += p[c];
    }
    #pragma unroll
    for (int o = 16; o; o >>= 1) {
        pn2 += __shfl_xor_sync(0xFFFFFFFFu, pn2, o);
        dt  += __shfl_xor_sync(0xFFFFFFFFu, dt, o);
    }
    __syncthreads();
    if (lane == 0) { red[2 * w] = pn2; red[2 * w + 1] = dt; }
    __syncthreads();
    if (tid == 0) {
        float P2 = 0.f, D = 0.f;
        #pragma unroll
        for (int r = 0; r < 16; r++) { P2 += red[2 * r]; D += red[2 * r + 1]; }
        const float pn = sqrtf(P2);
        float tension;
        if (pl) {
            const float overlap = D / (pn * sqrtf((float)KSEL) + EPSC);
            tension = (pn > 0.0f) ? (1.0f - overlap) : 1.0f;
        } else {
            const float xn = sqrtf((float)g_act_cntfull[t + 1]);
            tension = 1.0f - D / (pn * xn + EPSC);
        }
        out[t] = tension;
    }
}

// ---------------- launch ------------------------------------------------------
extern "C" void kernel_launch(void* const* d_in, const int* in_sizes, int n_in,
                              void* d_out, int out_size) {
    const int*   tokens = (const int*)d_in[0];
    const float* proj   = (const float*)d_in[1];
    const float* sigma  = (const float*)d_in[2];
    const int*   plast  = (const int*)d_in[3];
    float*       out    = (float*)d_out;

    k_topk<<<TT, 512>>>(tokens, proj);

    // k_mid with programmatic dependent launch (prologue overlaps k_topk)
    {
        cudaLaunchConfig_t cfg = {};
        cfg.gridDim  = dim3(NPAN);
        cfg.blockDim = dim3(512);
        cudaLaunchAttribute at[1];
        at[0].id = cudaLaunchAttributeProgrammaticStreamSerialization;
        at[0].val.programmaticStreamSerializationAllowed = 1;
        cfg.attrs = at;
        cfg.numAttrs = 1;
        cfg.stream = 0;
        if (cudaLaunchKernelEx(&cfg, k_mid, sigma) != cudaSuccess)
            k_mid<<<NPAN, 512>>>(sigma);
    }

    // k_tension with PDL (cw zeroing overlaps k_mid)
    {
        cudaLaunchConfig_t cfg = {};
        cfg.gridDim  = dim3(TT - 1);
        cfg.blockDim = dim3(512);
        cudaLaunchAttribute at[1];
        at[0].id = cudaLaunchAttributeProgrammaticStreamSerialization;
        at[0].val.programmaticStreamSerializationAllowed = 1;
        cfg.attrs = at;
        cfg.numAttrs = 1;
        cfg.stream = 0;
        if (cudaLaunchKernelEx(&cfg, k_tension, sigma, plast, out) != cudaSuccess)
            k_tension<<<TT - 1, 512>>>(sigma, plast, out);
    }
}